// round 13
// baseline (speedup 1.0000x reference)
#include <cuda_runtime.h>
#include <cuda_bf16.h>
#include <cstdint>

#define B_   64
#define TQ_  2048
#define TK_  2048
#define D_   64
#define STRW 68     // words per smem row (64 + 4 pad: conflict-free quad access)
#define MROWS 128   // q-rows per CTA
#define NT_  (TK_ / 64)

// Mask element kind: 1 = 1-byte elements (bool/uint8), 0 = 4-byte (int32/float32)
__device__ int g_mask_kind;

__global__ void detect_mask_kind(const unsigned char* __restrict__ m) {
    __shared__ int flag;
    int tid = threadIdx.x;
    if (tid == 0) flag = 0;
    __syncthreads();
    const uint4* m4 = (const uint4*)m;
    uint4 u = m4[tid];  // 256 threads * 16B = 4096 bytes
    unsigned w[4] = {u.x, u.y, u.z, u.w};
    int bad = 0;
#pragma unroll
    for (int i = 0; i < 4; i++) {
        unsigned x = w[i];
        if (!(x == 0u || x == 1u || x == 0x3F800000u)) bad = 1;
    }
    if (bad) atomicOr(&flag, 1);
    __syncthreads();
    if (tid == 0) g_mask_kind = flag ? 1 : 0;
}

// fast exp(s/8) via exp2: 5th-order poly, rel err ~3e-6.
__device__ __forceinline__ float fexp8(float s) {
    const float C = 0.18033688011112042f;  // log2(e)/8
    float z = fmaf(s, C, 12582912.0f);
    float nf = z - 12582912.0f;
    float f = fmaf(s, C, -nf);
    int n = __float_as_int(z) - 0x4B400000;
    float p = 1.3333558146e-3f;
    p = fmaf(p, f, 9.6181291076e-3f);
    p = fmaf(p, f, 5.5504108665e-2f);
    p = fmaf(p, f, 2.4022650696e-1f);
    p = fmaf(p, f, 6.9314718056e-1f);
    p = fmaf(p, f, 1.0f);
    return __int_as_float(__float_as_int(p) + (n << 23));
}

__device__ __forceinline__ unsigned cvt_tf32(float x) {
    unsigned r;
    asm("cvt.rna.tf32.f32 %0, %1;" : "=r"(r) : "f"(x));
    return r;
}

__device__ __forceinline__ void mma8(float c[4], const unsigned a[4],
                                     unsigned b0, unsigned b1) {
    asm("mma.sync.aligned.m16n8k8.row.col.f32.tf32.tf32.f32 "
        "{%0,%1,%2,%3}, {%4,%5,%6,%7}, {%8,%9}, {%0,%1,%2,%3};"
        : "+f"(c[0]), "+f"(c[1]), "+f"(c[2]), "+f"(c[3])
        : "r"(a[0]), "r"(a[1]), "r"(a[2]), "r"(a[3]), "r"(b0), "r"(b1));
}

__device__ __forceinline__ void cp16(void* sdst, const void* gsrc) {
    unsigned s = (unsigned)__cvta_generic_to_shared(sdst);
    asm volatile("cp.async.cg.shared.global [%0], [%1], 16;\n" :: "r"(s), "l"(gsrc));
}
__device__ __forceinline__ void cp_commit() {
    asm volatile("cp.async.commit_group;\n");
}
template <int N>
__device__ __forceinline__ void cp_wait() {
    asm volatile("cp.async.wait_group %0;\n" :: "n"(N));
}

// ---- TMA 1D bulk store helpers (smem -> gmem, per-thread bulk group) ----
__device__ __forceinline__ void bulk_s2g(void* gdst, const void* ssrc, int bytes) {
    unsigned s = (unsigned)__cvta_generic_to_shared(ssrc);
    asm volatile("cp.async.bulk.global.shared::cta.bulk_group [%0], [%1], %2;"
                 :: "l"(gdst), "r"(s), "r"(bytes) : "memory");
}
__device__ __forceinline__ void bulk_commit() {
    asm volatile("cp.async.bulk.commit_group;" ::: "memory");
}
__device__ __forceinline__ void bulk_wait_read0() {
    asm volatile("cp.async.bulk.wait_group.read 0;" ::: "memory");
}
__device__ __forceinline__ void bulk_wait_all() {
    asm volatile("cp.async.bulk.wait_group 0;" ::: "memory");
}
__device__ __forceinline__ void fence_async_proxy() {
    asm volatile("fence.proxy.async.shared::cta;" ::: "memory");
}

// ---------------------------------------------------------------------------
// Fused single pass, deferred-PV pipeline (R8 skeleton) + TMA bulk attn
// stores. CTA: 128 q-rows x full TK, 512 threads / 16 warps.
// Tile kt: (1) TMA bulk-store attn(kt-1) rows from Ps[prv] (no LDS/STG)
//          (2) prefetch V(kt), K/mask(kt+1) via cp.async
//          (3) QK(kt) mma  (4) exp -> Ps[cur]  (5) PV(kt-1) mma
//          (6) bulk read-wait + cp.async wait + one __syncthreads.
// ---------------------------------------------------------------------------
__global__ __launch_bounds__(512, 1)
void attn_fused(const float* __restrict__ q, const float* __restrict__ k,
                const float* __restrict__ v, const unsigned char* __restrict__ mask,
                float* __restrict__ out, float* __restrict__ attn) {
    extern __shared__ __align__(16) unsigned char smemraw[];
    float* Kb = (float*)smemraw;                         // [2][64][STRW] f32 K
    float* Vb = Kb + 2 * 64 * STRW;                      // [2][64][STRW] f32 V
    float* Psb = Vb + 2 * 64 * STRW;                     // [2][128][STRW] f32 e
    unsigned char* Msb = (unsigned char*)(Psb + 2 * MROWS * STRW);  // [2][128*80]
    float* RowRed = (float*)(Msb + 2 * MROWS * 80);      // [128]

#define KS(st, r, c) Kb[(st) * (64 * STRW) + (r) * STRW + (c)]
#define VS(st, r, c) Vb[(st) * (64 * STRW) + (r) * STRW + (c)]
#define PS(st, r, c) Psb[(st) * (MROWS * STRW) + (r) * STRW + (c)]
#define MS(st, i)    Msb[(st) * (MROWS * 80) + (i)]

    const int tid = threadIdx.x;
    const int wid = tid >> 5;
    const int lane = tid & 31;
    const int bb = blockIdx.y;
    const int qbase = blockIdx.x * MROWS;

    const float* qp = q + ((size_t)bb * TQ_ + qbase) * D_;
    const float* kp = k + (size_t)bb * TK_ * D_;
    const float* vp = v + (size_t)bb * TK_ * D_;
    float* arow = attn + ((size_t)bb * TQ_ + qbase) * TK_;
    const size_t mbase = ((size_t)bb * TQ_ + qbase) * TK_;
    const int mask_is_byte = g_mask_kind;

    if (tid < MROWS) RowRed[tid] = 0.0f;

    // K/V staging coords: 64x64 f32 tile, 512 threads -> 2 chunks of 16B each
    const int rr = tid >> 4;          // 0..31 ; rows rr, rr+32
    const int c4 = (tid & 15) * 4;
    // byte-mask staging: 128 rows x 64B -> 1 chunk of 16B per thread
    const int mr = tid >> 2;          // 0..127
    const int mseg = (tid & 3) * 16;

    // ---- prologue: prefetch K(0), mask(0) ----
#pragma unroll
    for (int j = 0; j < 2; j++)
        cp16(&KS(0, rr + j * 32, c4), kp + (size_t)(rr + j * 32) * D_ + c4);
    if (mask_is_byte) {
        cp16(&MS(0, mr * 80 + mseg), mask + mbase + (size_t)mr * TK_ + mseg);
    } else {
        const int* mi = (const int*)mask;
#pragma unroll
        for (int j = 0; j < 4; j++) {
            int i4 = tid + j * 512;
            int r = i4 >> 4, cc = (i4 & 15) * 4;
            int4 mm = *(const int4*)(mi + mbase + (size_t)r * TK_ + cc);
            uchar4 pk;
            pk.x = mm.x ? 1 : 0; pk.y = mm.y ? 1 : 0;
            pk.z = mm.z ? 1 : 0; pk.w = mm.w ? 1 : 0;
            *(uchar4*)&MS(0, r * 80 + cc) = pk;
        }
    }
    cp_commit();

    // Stage Q (128x64) into Ps[0] (raw f32), then to tf32 A fragments
#pragma unroll
    for (int j = 0; j < 4; j++) {
        int r = rr + j * 32;
        *(float4*)&PS(0, r, c4) = *(const float4*)(qp + r * D_ + c4);
    }
    __syncthreads();

    const int rg = wid >> 1;                 // 0..7
    const int kg = wid & 1;
    const int r0 = rg * 16 + (lane >> 2);    // 0..127
    const int qc = lane & 3;

    unsigned qa[8][4];
#pragma unroll
    for (int kc = 0; kc < 8; kc++) {
        qa[kc][0] = cvt_tf32(PS(0, r0, kc * 8 + qc));
        qa[kc][1] = cvt_tf32(PS(0, r0 + 8, kc * 8 + qc));
        qa[kc][2] = cvt_tf32(PS(0, r0, kc * 8 + qc + 4));
        qa[kc][3] = cvt_tf32(PS(0, r0 + 8, kc * 8 + qc + 4));
    }
    cp_wait<0>();     // K0/M0 arrived
    __syncthreads();  // qa built; Ps[0] free; K tile visible to all

    float oacc[4][4];
#pragma unroll
    for (int nt = 0; nt < 4; nt++)
#pragma unroll
        for (int i = 0; i < 4; i++) oacc[nt][i] = 0.0f;
    float rs0 = 0.0f, rs1 = 0.0f;

    for (int kt = 0; kt < NT_; kt++) {
        const int kb = kt * 64;
        const int cur = kt & 1;
        const int prv = cur ^ 1;

        // --- (1) TMA bulk store attn(kt-1): one 256B row per thread<128 ---
        if (kt > 0 && tid < MROWS) {
            fence_async_proxy();  // STS(Ps[prv]) ordered before async-proxy read
            bulk_s2g(arow + (size_t)tid * TK_ + (kb - 64), &PS(prv, tid, 0), 256);
            bulk_commit();
        }

        // --- (2) prefetch: V(kt) -> Vb[cur]; K(kt+1)+mask(kt+1) -> [prv] ---
#pragma unroll
        for (int j = 0; j < 2; j++) {
            int r = rr + j * 32;
            cp16(&VS(cur, r, c4), vp + (size_t)(kb + r) * D_ + c4);
        }
        if (kt + 1 < NT_) {
            const int kb2 = kb + 64;
#pragma unroll
            for (int j = 0; j < 2; j++) {
                int r = rr + j * 32;
                cp16(&KS(prv, r, c4), kp + (size_t)(kb2 + r) * D_ + c4);
            }
            if (mask_is_byte) {
                cp16(&MS(prv, mr * 80 + mseg),
                     mask + mbase + (size_t)mr * TK_ + kb2 + mseg);
            } else {
                const int* mi = (const int*)mask;
#pragma unroll
                for (int j = 0; j < 4; j++) {
                    int i4 = tid + j * 512;
                    int r = i4 >> 4, cc = (i4 & 15) * 4;
                    int4 mm = *(const int4*)(mi + mbase + (size_t)r * TK_ + kb2 + cc);
                    uchar4 pk;
                    pk.x = mm.x ? 1 : 0; pk.y = mm.y ? 1 : 0;
                    pk.z = mm.z ? 1 : 0; pk.w = mm.w ? 1 : 0;
                    *(uchar4*)&MS(prv, r * 80 + cc) = pk;
                }
            }
        }
        cp_commit();

        // --- (3) S = Q * K^T for this warp's 16x32 subtile (tile kt) ---
        float c[4][4];
#pragma unroll
        for (int nt = 0; nt < 4; nt++)
#pragma unroll
            for (int i = 0; i < 4; i++) c[nt][i] = 0.0f;

#pragma unroll
        for (int kc = 0; kc < 8; kc++) {
#pragma unroll
            for (int nt = 0; nt < 4; nt++) {
                int key = kg * 32 + nt * 8 + (lane >> 2);
                unsigned b0 = cvt_tf32(KS(cur, key, kc * 8 + qc));
                unsigned b1 = cvt_tf32(KS(cur, key, kc * 8 + qc + 4));
                mma8(c[nt], qa[kc], b0, b1);
            }
        }

        // --- (4) mask + exp -> Ps[cur], rowsum in regs ---
#pragma unroll
        for (int nt = 0; nt < 4; nt++) {
            int col = kg * 32 + nt * 8 + 2 * qc;
            float e00 = MS(cur, r0 * 80 + col)           ? 0.0f : fexp8(c[nt][0]);
            float e01 = MS(cur, r0 * 80 + col + 1)       ? 0.0f : fexp8(c[nt][1]);
            float e10 = MS(cur, (r0 + 8) * 80 + col)     ? 0.0f : fexp8(c[nt][2]);
            float e11 = MS(cur, (r0 + 8) * 80 + col + 1) ? 0.0f : fexp8(c[nt][3]);
            *(float2*)&PS(cur, r0, col) = make_float2(e00, e01);
            *(float2*)&PS(cur, r0 + 8, col) = make_float2(e10, e11);
            rs0 += e00 + e01;
            rs1 += e10 + e11;
        }

        // --- (5) deferred: PV(kt-1) from Ps[prv]/V[prv] ---
        if (kt > 0) {
#pragma unroll
            for (int kc = 0; kc < 8; kc++) {
                unsigned a[4];
                a[0] = cvt_tf32(PS(prv, r0, kc * 8 + qc));
                a[1] = cvt_tf32(PS(prv, r0 + 8, kc * 8 + qc));
                a[2] = cvt_tf32(PS(prv, r0, kc * 8 + qc + 4));
                a[3] = cvt_tf32(PS(prv, r0 + 8, kc * 8 + qc + 4));
#pragma unroll
                for (int nt = 0; nt < 4; nt++) {
                    int dcol = kg * 32 + nt * 8 + (lane >> 2);
                    unsigned b0 = cvt_tf32(VS(prv, kc * 8 + qc, dcol));
                    unsigned b1 = cvt_tf32(VS(prv, kc * 8 + qc + 4, dcol));
                    mma8(oacc[nt], a, b0, b1);
                }
            }
        }

        // --- (6) drains: TMA read of Ps[prv] done BEFORE the sync, so the
        //     next tile's STS into that buffer (by any thread) is safe ---
        if (kt > 0 && tid < MROWS) bulk_wait_read0();
        cp_wait<0>();     // V(kt), K(kt+1), mask(kt+1) landed
        __syncthreads();  // publishes Ps[cur]; guards all buffer reuse
    }

    // ---- flush: TMA store + PV for the last tile ----
    {
        const int lst = (NT_ - 1) & 1;
        const int kb = (NT_ - 1) * 64;
        if (tid < MROWS) {
            fence_async_proxy();
            bulk_s2g(arow + (size_t)tid * TK_ + kb, &PS(lst, tid, 0), 256);
            bulk_commit();
        }
#pragma unroll
        for (int kc = 0; kc < 8; kc++) {
            unsigned a[4];
            a[0] = cvt_tf32(PS(lst, r0, kc * 8 + qc));
            a[1] = cvt_tf32(PS(lst, r0 + 8, kc * 8 + qc));
            a[2] = cvt_tf32(PS(lst, r0, kc * 8 + qc + 4));
            a[3] = cvt_tf32(PS(lst, r0 + 8, kc * 8 + qc + 4));
#pragma unroll
            for (int nt = 0; nt < 4; nt++) {
                int dcol = kg * 32 + nt * 8 + (lane >> 2);
                unsigned b0 = cvt_tf32(VS(lst, kc * 8 + qc, dcol));
                unsigned b1 = cvt_tf32(VS(lst, kc * 8 + qc + 4, dcol));
                mma8(oacc[nt], a, b0, b1);
            }
        }
        if (tid < MROWS) bulk_wait_all();  // writes visible before rescale reads
    }

    // ---- rowsum reduction: quad lanes, then the two kg warps per rowgroup ----
    rs0 += __shfl_xor_sync(0xFFFFFFFFu, rs0, 1);
    rs0 += __shfl_xor_sync(0xFFFFFFFFu, rs0, 2);
    rs1 += __shfl_xor_sync(0xFFFFFFFFu, rs1, 1);
    rs1 += __shfl_xor_sync(0xFFFFFFFFu, rs1, 2);
    if (qc == 0) {
        atomicAdd(&RowRed[r0], rs0);
        atomicAdd(&RowRed[r0 + 8], rs1);
    }
    __syncthreads();
    if (tid < MROWS) RowRed[tid] = 1.0f / RowRed[tid];
    __syncthreads();

    // ---- write O scaled by 1/rowsum ----
    {
        float inv0 = RowRed[r0];
        float inv1 = RowRed[r0 + 8];
#pragma unroll
        for (int nt = 0; nt < 4; nt++) {
            int dcol = kg * 32 + nt * 8 + 2 * qc;
            size_t oi = ((size_t)(bb * TQ_ + qbase + r0)) * D_ + dcol;
            *(float2*)(out + oi) =
                make_float2(oacc[nt][0] * inv0, oacc[nt][1] * inv0);
            *(float2*)(out + oi + (size_t)8 * D_) =
                make_float2(oacc[nt][2] * inv1, oacc[nt][3] * inv1);
        }
    }

    // ---- in-place normalize of this CTA's attn slice, newest tiles first ----
    for (int tt = NT_ - 1; tt >= 0; --tt) {
        const int kb = tt * 64;
#pragma unroll
        for (int j = 0; j < 4; j++) {
            int i = tid + j * 512;          // 2048 float4 per 128x64 tile
            int r = i >> 4, cc = (i & 15) * 4;
            float inv = RowRed[r];
            float4* p4 = (float4*)(arow + (size_t)r * TK_ + kb + cc);
            float4 x = *p4;
            x.x *= inv; x.y *= inv; x.z *= inv; x.w *= inv;
            *p4 = x;
        }
    }
}

static const int kSmemBytes =
    (2 * 64 * STRW + 2 * 64 * STRW + 2 * MROWS * STRW) * 4 + 2 * MROWS * 80 + MROWS * 4;

extern "C" void kernel_launch(void* const* d_in, const int* in_sizes, int n_in,
                              void* d_out, int out_size) {
    const float* q = (const float*)d_in[0];
    const float* k = (const float*)d_in[1];
    const float* v = (const float*)d_in[2];
    const unsigned char* mask = (const unsigned char*)d_in[3];

    float* out = (float*)d_out;                 // [B, TQ, D]
    float* attn = out + (size_t)B_ * TQ_ * D_;  // [B, TQ, TK]

    cudaFuncSetAttribute(attn_fused, cudaFuncAttributeMaxDynamicSharedMemorySize,
                         kSmemBytes);

    detect_mask_kind<<<1, 256>>>(mask);

    dim3 grid(TQ_ / MROWS, B_);
    attn_fused<<<grid, 512, kSmemBytes>>>(q, k, v, mask, out, attn);
}

// round 14
// speedup vs baseline: 1.1268x; 1.1268x over previous
#include <cuda_runtime.h>
#include <cuda_bf16.h>
#include <cstdint>

#define B_   64
#define TQ_  2048
#define TK_  2048
#define D_   64
#define STRW 68     // words per smem row (64 + 4 pad: conflict-free quad access)
#define MROWS 128   // q-rows per CTA
#define NT_  (TK_ / 64)

// Per-row 1/rowsum, main kernel -> rescale kernel. Static device scratch.
__device__ float g_rowinv[B_ * TQ_];
// Mask element kind: 1 = 1-byte elements (bool/uint8), 0 = 4-byte (int32/float32)
__device__ int g_mask_kind;

__global__ void detect_mask_kind(const unsigned char* __restrict__ m) {
    __shared__ int flag;
    int tid = threadIdx.x;
    if (tid == 0) flag = 0;
    __syncthreads();
    const uint4* m4 = (const uint4*)m;
    uint4 u = m4[tid];  // 256 threads * 16B = 4096 bytes
    unsigned w[4] = {u.x, u.y, u.z, u.w};
    int bad = 0;
#pragma unroll
    for (int i = 0; i < 4; i++) {
        unsigned x = w[i];
        if (!(x == 0u || x == 1u || x == 0x3F800000u)) bad = 1;
    }
    if (bad) atomicOr(&flag, 1);
    __syncthreads();
    if (tid == 0) g_mask_kind = flag ? 1 : 0;
}

// fast exp(s/8) via exp2: 5th-order poly, rel err ~3e-6.
__device__ __forceinline__ float fexp8(float s) {
    const float C = 0.18033688011112042f;  // log2(e)/8
    float z = fmaf(s, C, 12582912.0f);
    float nf = z - 12582912.0f;
    float f = fmaf(s, C, -nf);
    int n = __float_as_int(z) - 0x4B400000;
    float p = 1.3333558146e-3f;
    p = fmaf(p, f, 9.6181291076e-3f);
    p = fmaf(p, f, 5.5504108665e-2f);
    p = fmaf(p, f, 2.4022650696e-1f);
    p = fmaf(p, f, 6.9314718056e-1f);
    p = fmaf(p, f, 1.0f);
    return __int_as_float(__float_as_int(p) + (n << 23));
}

__device__ __forceinline__ unsigned cvt_tf32(float x) {
    unsigned r;
    asm("cvt.rna.tf32.f32 %0, %1;" : "=r"(r) : "f"(x));
    return r;
}

__device__ __forceinline__ void mma8(float c[4], const unsigned a[4],
                                     unsigned b0, unsigned b1) {
    asm("mma.sync.aligned.m16n8k8.row.col.f32.tf32.tf32.f32 "
        "{%0,%1,%2,%3}, {%4,%5,%6,%7}, {%8,%9}, {%0,%1,%2,%3};"
        : "+f"(c[0]), "+f"(c[1]), "+f"(c[2]), "+f"(c[3])
        : "r"(a[0]), "r"(a[1]), "r"(a[2]), "r"(a[3]), "r"(b0), "r"(b1));
}

__device__ __forceinline__ void cp16(void* sdst, const void* gsrc) {
    unsigned s = (unsigned)__cvta_generic_to_shared(sdst);
    asm volatile("cp.async.cg.shared.global [%0], [%1], 16;\n" :: "r"(s), "l"(gsrc));
}
__device__ __forceinline__ void cp_commit() {
    asm volatile("cp.async.commit_group;\n");
}
template <int N>
__device__ __forceinline__ void cp_wait() {
    asm volatile("cp.async.wait_group %0;\n" :: "n"(N));
}

// ---------------------------------------------------------------------------
// Fused mainloop (R8 skeleton, best known). CTA: 128 q-rows x full TK,
// 512 threads / 16 warps. Writes UNNORMALIZED attn; per-row inverses go to
// g_rowinv; normalization happens in rescale_attn (separate streaming kernel).
// ---------------------------------------------------------------------------
__global__ __launch_bounds__(512, 1)
void attn_fused(const float* __restrict__ q, const float* __restrict__ k,
                const float* __restrict__ v, const unsigned char* __restrict__ mask,
                float* __restrict__ out, float* __restrict__ attn) {
    extern __shared__ __align__(16) unsigned char smemraw[];
    float* Kb = (float*)smemraw;                         // [2][64][STRW] f32 K
    float* Vb = Kb + 2 * 64 * STRW;                      // [2][64][STRW] f32 V
    float* Psb = Vb + 2 * 64 * STRW;                     // [2][128][STRW] f32 e
    unsigned char* Msb = (unsigned char*)(Psb + 2 * MROWS * STRW);  // [2][128*80]
    float* RowRed = (float*)(Msb + 2 * MROWS * 80);      // [128]

#define KS(st, r, c) Kb[(st) * (64 * STRW) + (r) * STRW + (c)]
#define VS(st, r, c) Vb[(st) * (64 * STRW) + (r) * STRW + (c)]
#define PS(st, r, c) Psb[(st) * (MROWS * STRW) + (r) * STRW + (c)]
#define MS(st, i)    Msb[(st) * (MROWS * 80) + (i)]

    const int tid = threadIdx.x;
    const int wid = tid >> 5;
    const int lane = tid & 31;
    const int bb = blockIdx.y;
    const int qbase = blockIdx.x * MROWS;

    const float* qp = q + ((size_t)bb * TQ_ + qbase) * D_;
    const float* kp = k + (size_t)bb * TK_ * D_;
    const float* vp = v + (size_t)bb * TK_ * D_;
    float* arow = attn + ((size_t)bb * TQ_ + qbase) * TK_;
    const size_t mbase = ((size_t)bb * TQ_ + qbase) * TK_;
    const int mask_is_byte = g_mask_kind;

    if (tid < MROWS) RowRed[tid] = 0.0f;

    // K/V staging coords: 64x64 f32 tile, 512 threads -> 2 chunks of 16B each
    const int rr = tid >> 4;          // 0..31 ; rows rr, rr+32
    const int c4 = (tid & 15) * 4;
    // byte-mask staging: 128 rows x 64B -> 1 chunk of 16B per thread
    const int mr = tid >> 2;          // 0..127
    const int mseg = (tid & 3) * 16;

    // ---- prologue: prefetch K(0), mask(0) ----
#pragma unroll
    for (int j = 0; j < 2; j++)
        cp16(&KS(0, rr + j * 32, c4), kp + (size_t)(rr + j * 32) * D_ + c4);
    if (mask_is_byte) {
        cp16(&MS(0, mr * 80 + mseg), mask + mbase + (size_t)mr * TK_ + mseg);
    } else {
        const int* mi = (const int*)mask;
#pragma unroll
        for (int j = 0; j < 4; j++) {
            int i4 = tid + j * 512;
            int r = i4 >> 4, cc = (i4 & 15) * 4;
            int4 mm = *(const int4*)(mi + mbase + (size_t)r * TK_ + cc);
            uchar4 pk;
            pk.x = mm.x ? 1 : 0; pk.y = mm.y ? 1 : 0;
            pk.z = mm.z ? 1 : 0; pk.w = mm.w ? 1 : 0;
            *(uchar4*)&MS(0, r * 80 + cc) = pk;
        }
    }
    cp_commit();

    // Stage Q (128x64) into Ps[0] (raw f32), then to tf32 A fragments
#pragma unroll
    for (int j = 0; j < 4; j++) {
        int r = rr + j * 32;
        *(float4*)&PS(0, r, c4) = *(const float4*)(qp + r * D_ + c4);
    }
    __syncthreads();

    const int rg = wid >> 1;                 // 0..7
    const int kg = wid & 1;
    const int r0 = rg * 16 + (lane >> 2);    // 0..127
    const int qc = lane & 3;

    unsigned qa[8][4];
#pragma unroll
    for (int kc = 0; kc < 8; kc++) {
        qa[kc][0] = cvt_tf32(PS(0, r0, kc * 8 + qc));
        qa[kc][1] = cvt_tf32(PS(0, r0 + 8, kc * 8 + qc));
        qa[kc][2] = cvt_tf32(PS(0, r0, kc * 8 + qc + 4));
        qa[kc][3] = cvt_tf32(PS(0, r0 + 8, kc * 8 + qc + 4));
    }
    cp_wait<0>();     // K0/M0 arrived
    __syncthreads();  // qa built; Ps[0] free; K tile visible to all

    float oacc[4][4];
#pragma unroll
    for (int nt = 0; nt < 4; nt++)
#pragma unroll
        for (int i = 0; i < 4; i++) oacc[nt][i] = 0.0f;
    float rs0 = 0.0f, rs1 = 0.0f;

    for (int kt = 0; kt < NT_; kt++) {
        const int kb = kt * 64;
        const int cur = kt & 1;
        const int prv = cur ^ 1;

        // --- prefetch: V(kt) -> Vb[cur]; K(kt+1)+mask(kt+1) -> [cur^1] ---
#pragma unroll
        for (int j = 0; j < 2; j++) {
            int r = rr + j * 32;
            cp16(&VS(cur, r, c4), vp + (size_t)(kb + r) * D_ + c4);
        }
        if (kt + 1 < NT_) {
            const int kb2 = kb + 64;
#pragma unroll
            for (int j = 0; j < 2; j++) {
                int r = rr + j * 32;
                cp16(&KS(prv, r, c4), kp + (size_t)(kb2 + r) * D_ + c4);
            }
            if (mask_is_byte) {
                cp16(&MS(prv, mr * 80 + mseg),
                     mask + mbase + (size_t)mr * TK_ + kb2 + mseg);
            } else {
                const int* mi = (const int*)mask;
#pragma unroll
                for (int j = 0; j < 4; j++) {
                    int i4 = tid + j * 512;
                    int r = i4 >> 4, cc = (i4 & 15) * 4;
                    int4 mm = *(const int4*)(mi + mbase + (size_t)r * TK_ + kb2 + cc);
                    uchar4 pk;
                    pk.x = mm.x ? 1 : 0; pk.y = mm.y ? 1 : 0;
                    pk.z = mm.z ? 1 : 0; pk.w = mm.w ? 1 : 0;
                    *(uchar4*)&MS(prv, r * 80 + cc) = pk;
                }
            }
        }
        cp_commit();

        // --- S = Q * K^T for this warp's 16x32 subtile (tile kt) ---
        float c[4][4];
#pragma unroll
        for (int nt = 0; nt < 4; nt++)
#pragma unroll
            for (int i = 0; i < 4; i++) c[nt][i] = 0.0f;

#pragma unroll
        for (int kc = 0; kc < 8; kc++) {
#pragma unroll
            for (int nt = 0; nt < 4; nt++) {
                int key = kg * 32 + nt * 8 + (lane >> 2);
                unsigned b0 = cvt_tf32(KS(cur, key, kc * 8 + qc));
                unsigned b1 = cvt_tf32(KS(cur, key, kc * 8 + qc + 4));
                mma8(c[nt], qa[kc], b0, b1);
            }
        }

        // --- mask + exp -> Ps[cur], rowsum in regs ---
#pragma unroll
        for (int nt = 0; nt < 4; nt++) {
            int col = kg * 32 + nt * 8 + 2 * qc;
            float e00 = MS(cur, r0 * 80 + col)           ? 0.0f : fexp8(c[nt][0]);
            float e01 = MS(cur, r0 * 80 + col + 1)       ? 0.0f : fexp8(c[nt][1]);
            float e10 = MS(cur, (r0 + 8) * 80 + col)     ? 0.0f : fexp8(c[nt][2]);
            float e11 = MS(cur, (r0 + 8) * 80 + col + 1) ? 0.0f : fexp8(c[nt][3]);
            *(float2*)&PS(cur, r0, col) = make_float2(e00, e01);
            *(float2*)&PS(cur, r0 + 8, col) = make_float2(e10, e11);
            rs0 += e00 + e01;
            rs1 += e10 + e11;
        }

        // --- deferred: PV(kt-1) + attn store(kt-1) from Ps[prv]/V[prv] ---
        if (kt > 0) {
#pragma unroll
            for (int kc = 0; kc < 8; kc++) {
                unsigned a[4];
                a[0] = cvt_tf32(PS(prv, r0, kc * 8 + qc));
                a[1] = cvt_tf32(PS(prv, r0 + 8, kc * 8 + qc));
                a[2] = cvt_tf32(PS(prv, r0, kc * 8 + qc + 4));
                a[3] = cvt_tf32(PS(prv, r0 + 8, kc * 8 + qc + 4));
#pragma unroll
                for (int nt = 0; nt < 4; nt++) {
                    int dcol = kg * 32 + nt * 8 + (lane >> 2);
                    unsigned b0 = cvt_tf32(VS(prv, kc * 8 + qc, dcol));
                    unsigned b1 = cvt_tf32(VS(prv, kc * 8 + qc + 4, dcol));
                    mma8(oacc[nt], a, b0, b1);
                }
            }
#pragma unroll
            for (int j = 0; j < 4; j++) {
                int i = tid + j * 512;
                int r = i >> 4, cc = (i & 15) * 4;
                *(float4*)(arow + (size_t)r * TK_ + (kb - 64) + cc) =
                    *(float4*)&PS(prv, r, cc);
            }
        }

        cp_wait<0>();     // V(kt), K(kt+1), mask(kt+1) landed
        __syncthreads();  // publishes Ps[cur]; guards all buffer reuse
    }

    // ---- flush: PV + attn store for the last tile ----
    {
        const int lst = (NT_ - 1) & 1;
        const int kb = (NT_ - 1) * 64;
#pragma unroll
        for (int j = 0; j < 4; j++) {
            int i = tid + j * 512;
            int r = i >> 4, cc = (i & 15) * 4;
            *(float4*)(arow + (size_t)r * TK_ + kb + cc) = *(float4*)&PS(lst, r, cc);
        }
#pragma unroll
        for (int kc = 0; kc < 8; kc++) {
            unsigned a[4];
            a[0] = cvt_tf32(PS(lst, r0, kc * 8 + qc));
            a[1] = cvt_tf32(PS(lst, r0 + 8, kc * 8 + qc));
            a[2] = cvt_tf32(PS(lst, r0, kc * 8 + qc + 4));
            a[3] = cvt_tf32(PS(lst, r0 + 8, kc * 8 + qc + 4));
#pragma unroll
            for (int nt = 0; nt < 4; nt++) {
                int dcol = kg * 32 + nt * 8 + (lane >> 2);
                unsigned b0 = cvt_tf32(VS(lst, kc * 8 + qc, dcol));
                unsigned b1 = cvt_tf32(VS(lst, kc * 8 + qc + 4, dcol));
                mma8(oacc[nt], a, b0, b1);
            }
        }
    }

    // ---- rowsum reduction: quad lanes, then the two kg warps per rowgroup ----
    rs0 += __shfl_xor_sync(0xFFFFFFFFu, rs0, 1);
    rs0 += __shfl_xor_sync(0xFFFFFFFFu, rs0, 2);
    rs1 += __shfl_xor_sync(0xFFFFFFFFu, rs1, 1);
    rs1 += __shfl_xor_sync(0xFFFFFFFFu, rs1, 2);
    if (qc == 0) {
        atomicAdd(&RowRed[r0], rs0);
        atomicAdd(&RowRed[r0 + 8], rs1);
    }
    __syncthreads();
    if (tid < MROWS) {
        float inv = 1.0f / RowRed[tid];
        RowRed[tid] = inv;
        g_rowinv[bb * TQ_ + qbase + tid] = inv;   // publish for rescale kernel
    }
    __syncthreads();

    // ---- write O scaled by 1/rowsum ----
    {
        float inv0 = RowRed[r0];
        float inv1 = RowRed[r0 + 8];
#pragma unroll
        for (int nt = 0; nt < 4; nt++) {
            int dcol = kg * 32 + nt * 8 + 2 * qc;
            size_t oi = ((size_t)(bb * TQ_ + qbase + r0)) * D_ + dcol;
            *(float2*)(out + oi) =
                make_float2(oacc[nt][0] * inv0, oacc[nt][1] * inv0);
            *(float2*)(out + oi + (size_t)8 * D_) =
                make_float2(oacc[nt][2] * inv1, oacc[nt][3] * inv1);
        }
    }
}

// ---------------------------------------------------------------------------
// Streaming normalize: attn[i] *= g_rowinv[row(i)]. Tiny register footprint,
// full occupancy, coalesced float4 grid-stride -> near-peak DRAM.
// ---------------------------------------------------------------------------
__global__ __launch_bounds__(256)
void rescale_attn(float* __restrict__ attn) {
    const size_t N4 = (size_t)B_ * TQ_ * TK_ / 4;   // 67,108,864 float4
    size_t i = (size_t)blockIdx.x * blockDim.x + threadIdx.x;
    const size_t stride = (size_t)gridDim.x * blockDim.x;
    float4* a4 = (float4*)attn;
    for (; i < N4; i += stride) {
        float inv = g_rowinv[i >> 9];               // 512 float4 per attn row
        float4 x = a4[i];
        x.x *= inv; x.y *= inv; x.z *= inv; x.w *= inv;
        a4[i] = x;
    }
}

static const int kSmemBytes =
    (2 * 64 * STRW + 2 * 64 * STRW + 2 * MROWS * STRW) * 4 + 2 * MROWS * 80 + MROWS * 4;

extern "C" void kernel_launch(void* const* d_in, const int* in_sizes, int n_in,
                              void* d_out, int out_size) {
    const float* q = (const float*)d_in[0];
    const float* k = (const float*)d_in[1];
    const float* v = (const float*)d_in[2];
    const unsigned char* mask = (const unsigned char*)d_in[3];

    float* out = (float*)d_out;                 // [B, TQ, D]
    float* attn = out + (size_t)B_ * TQ_ * D_;  // [B, TQ, TK]

    cudaFuncSetAttribute(attn_fused, cudaFuncAttributeMaxDynamicSharedMemorySize,
                         kSmemBytes);

    detect_mask_kind<<<1, 256>>>(mask);

    dim3 grid(TQ_ / MROWS, B_);
    attn_fused<<<grid, 512, kSmemBytes>>>(q, k, v, mask, out, attn);

    // 16384 blocks x 256 thr, 16 float4 each: full coverage, grid-stride safe.
    rescale_attn<<<16384, 256>>>(attn);
}

// round 15
// speedup vs baseline: 1.1289x; 1.0019x over previous
#include <cuda_runtime.h>
#include <cuda_bf16.h>
#include <cstdint>

#define B_   64
#define TQ_  2048
#define TK_  2048
#define D_   64
#define STRW 68     // words per smem row (64 + 4 pad: conflict-free quad access)
#define MROWS 128   // q-rows per CTA
#define NT_  (TK_ / 64)

// Per-row 1/rowsum, main kernel -> rescale kernel. Static device scratch.
__device__ float g_rowinv[B_ * TQ_];
// Mask element kind: 1 = 1-byte elements (bool/uint8), 0 = 4-byte (int32/float32)
__device__ int g_mask_kind;

__global__ void detect_mask_kind(const unsigned char* __restrict__ m) {
    __shared__ int flag;
    int tid = threadIdx.x;
    if (tid == 0) flag = 0;
    __syncthreads();
    const uint4* m4 = (const uint4*)m;
    uint4 u = m4[tid];  // 256 threads * 16B = 4096 bytes
    unsigned w[4] = {u.x, u.y, u.z, u.w};
    int bad = 0;
#pragma unroll
    for (int i = 0; i < 4; i++) {
        unsigned x = w[i];
        if (!(x == 0u || x == 1u || x == 0x3F800000u)) bad = 1;
    }
    if (bad) atomicOr(&flag, 1);
    __syncthreads();
    if (tid == 0) g_mask_kind = flag ? 1 : 0;
}

// fast exp(s/8) via exp2: 5th-order poly, rel err ~3e-6.
__device__ __forceinline__ float fexp8(float s) {
    const float C = 0.18033688011112042f;  // log2(e)/8
    float z = fmaf(s, C, 12582912.0f);
    float nf = z - 12582912.0f;
    float f = fmaf(s, C, -nf);
    int n = __float_as_int(z) - 0x4B400000;
    float p = 1.3333558146e-3f;
    p = fmaf(p, f, 9.6181291076e-3f);
    p = fmaf(p, f, 5.5504108665e-2f);
    p = fmaf(p, f, 2.4022650696e-1f);
    p = fmaf(p, f, 6.9314718056e-1f);
    p = fmaf(p, f, 1.0f);
    return __int_as_float(__float_as_int(p) + (n << 23));
}

__device__ __forceinline__ unsigned cvt_tf32(float x) {
    unsigned r;
    asm("cvt.rna.tf32.f32 %0, %1;" : "=r"(r) : "f"(x));
    return r;
}

__device__ __forceinline__ void mma8(float c[4], const unsigned a[4],
                                     unsigned b0, unsigned b1) {
    asm("mma.sync.aligned.m16n8k8.row.col.f32.tf32.tf32.f32 "
        "{%0,%1,%2,%3}, {%4,%5,%6,%7}, {%8,%9}, {%0,%1,%2,%3};"
        : "+f"(c[0]), "+f"(c[1]), "+f"(c[2]), "+f"(c[3])
        : "r"(a[0]), "r"(a[1]), "r"(a[2]), "r"(a[3]), "r"(b0), "r"(b1));
}

__device__ __forceinline__ void cp16(void* sdst, const void* gsrc) {
    unsigned s = (unsigned)__cvta_generic_to_shared(sdst);
    asm volatile("cp.async.cg.shared.global [%0], [%1], 16;\n" :: "r"(s), "l"(gsrc));
}
__device__ __forceinline__ void cp_commit() {
    asm volatile("cp.async.commit_group;\n");
}
template <int N>
__device__ __forceinline__ void cp_wait() {
    asm volatile("cp.async.wait_group %0;\n" :: "n"(N));
}

// convert a 16B smem chunk of 4 f32 to tf32 bits, in place
__device__ __forceinline__ void cvt_chunk(float* p) {
    float4 x = *(float4*)p;
    uint4 u = make_uint4(cvt_tf32(x.x), cvt_tf32(x.y), cvt_tf32(x.z), cvt_tf32(x.w));
    *(uint4*)p = u;
}

// ---------------------------------------------------------------------------
// Fused mainloop (R8 skeleton + split rescale). CTA: 128 q-rows x full TK,
// 512 threads / 16 warps. K and V tiles are converted to tf32 IN PLACE at
// staging time (once), so all mma B operands are plain LDS -> HMMA.
// Writes UNNORMALIZED attn; per-row inverses -> g_rowinv; normalization in
// rescale_attn (separate streaming kernel).
// ---------------------------------------------------------------------------
__global__ __launch_bounds__(512, 1)
void attn_fused(const float* __restrict__ q, const float* __restrict__ k,
                const float* __restrict__ v, const unsigned char* __restrict__ mask,
                float* __restrict__ out, float* __restrict__ attn) {
    extern __shared__ __align__(16) unsigned char smemraw[];
    float* Kb = (float*)smemraw;                         // [2][64][STRW] tf32 K
    float* Vb = Kb + 2 * 64 * STRW;                      // [2][64][STRW] tf32 V
    float* Psb = Vb + 2 * 64 * STRW;                     // [2][128][STRW] f32 e
    unsigned char* Msb = (unsigned char*)(Psb + 2 * MROWS * STRW);  // [2][128*80]
    float* RowRed = (float*)(Msb + 2 * MROWS * 80);      // [128]

#define KS(st, r, c) Kb[(st) * (64 * STRW) + (r) * STRW + (c)]
#define VS(st, r, c) Vb[(st) * (64 * STRW) + (r) * STRW + (c)]
#define KSU(st, r, c) (*(unsigned*)&KS(st, r, c))
#define VSU(st, r, c) (*(unsigned*)&VS(st, r, c))
#define PS(st, r, c) Psb[(st) * (MROWS * STRW) + (r) * STRW + (c)]
#define MS(st, i)    Msb[(st) * (MROWS * 80) + (i)]

    const int tid = threadIdx.x;
    const int wid = tid >> 5;
    const int lane = tid & 31;
    const int bb = blockIdx.y;
    const int qbase = blockIdx.x * MROWS;

    const float* qp = q + ((size_t)bb * TQ_ + qbase) * D_;
    const float* kp = k + (size_t)bb * TK_ * D_;
    const float* vp = v + (size_t)bb * TK_ * D_;
    float* arow = attn + ((size_t)bb * TQ_ + qbase) * TK_;
    const size_t mbase = ((size_t)bb * TQ_ + qbase) * TK_;
    const int mask_is_byte = g_mask_kind;

    if (tid < MROWS) RowRed[tid] = 0.0f;

    // K/V staging coords: 64x64 f32 tile, 512 threads -> 2 chunks of 16B each
    const int rr = tid >> 4;          // 0..31 ; rows rr, rr+32
    const int c4 = (tid & 15) * 4;
    // byte-mask staging: 128 rows x 64B -> 1 chunk of 16B per thread
    const int mr = tid >> 2;          // 0..127
    const int mseg = (tid & 3) * 16;

    // ---- prologue: prefetch K(0), mask(0) ----
#pragma unroll
    for (int j = 0; j < 2; j++)
        cp16(&KS(0, rr + j * 32, c4), kp + (size_t)(rr + j * 32) * D_ + c4);
    if (mask_is_byte) {
        cp16(&MS(0, mr * 80 + mseg), mask + mbase + (size_t)mr * TK_ + mseg);
    } else {
        const int* mi = (const int*)mask;
#pragma unroll
        for (int j = 0; j < 4; j++) {
            int i4 = tid + j * 512;
            int r = i4 >> 4, cc = (i4 & 15) * 4;
            int4 mm = *(const int4*)(mi + mbase + (size_t)r * TK_ + cc);
            uchar4 pk;
            pk.x = mm.x ? 1 : 0; pk.y = mm.y ? 1 : 0;
            pk.z = mm.z ? 1 : 0; pk.w = mm.w ? 1 : 0;
            *(uchar4*)&MS(0, r * 80 + cc) = pk;
        }
    }
    cp_commit();

    // Stage Q (128x64) into Ps[0] (raw f32), then to tf32 A fragments
#pragma unroll
    for (int j = 0; j < 4; j++) {
        int r = rr + j * 32;
        *(float4*)&PS(0, r, c4) = *(const float4*)(qp + r * D_ + c4);
    }
    __syncthreads();

    const int rg = wid >> 1;                 // 0..7
    const int kg = wid & 1;
    const int r0 = rg * 16 + (lane >> 2);    // 0..127
    const int qc = lane & 3;

    unsigned qa[8][4];
#pragma unroll
    for (int kc = 0; kc < 8; kc++) {
        qa[kc][0] = cvt_tf32(PS(0, r0, kc * 8 + qc));
        qa[kc][1] = cvt_tf32(PS(0, r0 + 8, kc * 8 + qc));
        qa[kc][2] = cvt_tf32(PS(0, r0, kc * 8 + qc + 4));
        qa[kc][3] = cvt_tf32(PS(0, r0 + 8, kc * 8 + qc + 4));
    }
    cp_wait<0>();     // K0/M0 arrived
    // convert K(0) to tf32 in place (each thread converts what it staged)
#pragma unroll
    for (int j = 0; j < 2; j++) cvt_chunk(&KS(0, rr + j * 32, c4));
    __syncthreads();  // qa built; Ps[0] free; converted K tile visible to all

    float oacc[4][4];
#pragma unroll
    for (int nt = 0; nt < 4; nt++)
#pragma unroll
        for (int i = 0; i < 4; i++) oacc[nt][i] = 0.0f;
    float rs0 = 0.0f, rs1 = 0.0f;

    for (int kt = 0; kt < NT_; kt++) {
        const int kb = kt * 64;
        const int cur = kt & 1;
        const int prv = cur ^ 1;

        // --- prefetch: V(kt) -> Vb[cur]; K(kt+1)+mask(kt+1) -> [cur^1] ---
#pragma unroll
        for (int j = 0; j < 2; j++) {
            int r = rr + j * 32;
            cp16(&VS(cur, r, c4), vp + (size_t)(kb + r) * D_ + c4);
        }
        if (kt + 1 < NT_) {
            const int kb2 = kb + 64;
#pragma unroll
            for (int j = 0; j < 2; j++) {
                int r = rr + j * 32;
                cp16(&KS(prv, r, c4), kp + (size_t)(kb2 + r) * D_ + c4);
            }
            if (mask_is_byte) {
                cp16(&MS(prv, mr * 80 + mseg),
                     mask + mbase + (size_t)mr * TK_ + kb2 + mseg);
            } else {
                const int* mi = (const int*)mask;
#pragma unroll
                for (int j = 0; j < 4; j++) {
                    int i4 = tid + j * 512;
                    int r = i4 >> 4, cc = (i4 & 15) * 4;
                    int4 mm = *(const int4*)(mi + mbase + (size_t)r * TK_ + kb2 + cc);
                    uchar4 pk;
                    pk.x = mm.x ? 1 : 0; pk.y = mm.y ? 1 : 0;
                    pk.z = mm.z ? 1 : 0; pk.w = mm.w ? 1 : 0;
                    *(uchar4*)&MS(prv, r * 80 + cc) = pk;
                }
            }
        }
        cp_commit();

        // --- S = Q * K^T for this warp's 16x32 subtile (tile kt) ---
        // K already tf32: plain LDS -> HMMA (no cvt in the chain)
        float c[4][4];
#pragma unroll
        for (int nt = 0; nt < 4; nt++)
#pragma unroll
            for (int i = 0; i < 4; i++) c[nt][i] = 0.0f;

#pragma unroll
        for (int kc = 0; kc < 8; kc++) {
#pragma unroll
            for (int nt = 0; nt < 4; nt++) {
                int key = kg * 32 + nt * 8 + (lane >> 2);
                mma8(c[nt], qa[kc], KSU(cur, key, kc * 8 + qc),
                     KSU(cur, key, kc * 8 + qc + 4));
            }
        }

        // --- mask + exp -> Ps[cur], rowsum in regs ---
#pragma unroll
        for (int nt = 0; nt < 4; nt++) {
            int col = kg * 32 + nt * 8 + 2 * qc;
            float e00 = MS(cur, r0 * 80 + col)           ? 0.0f : fexp8(c[nt][0]);
            float e01 = MS(cur, r0 * 80 + col + 1)       ? 0.0f : fexp8(c[nt][1]);
            float e10 = MS(cur, (r0 + 8) * 80 + col)     ? 0.0f : fexp8(c[nt][2]);
            float e11 = MS(cur, (r0 + 8) * 80 + col + 1) ? 0.0f : fexp8(c[nt][3]);
            *(float2*)&PS(cur, r0, col) = make_float2(e00, e01);
            *(float2*)&PS(cur, r0 + 8, col) = make_float2(e10, e11);
            rs0 += e00 + e01;
            rs1 += e10 + e11;
        }

        // --- deferred: PV(kt-1) + attn store(kt-1) from Ps[prv]/V[prv] ---
        // V already tf32: plain LDS B operands
        if (kt > 0) {
#pragma unroll
            for (int kc = 0; kc < 8; kc++) {
                unsigned a[4];
                a[0] = cvt_tf32(PS(prv, r0, kc * 8 + qc));
                a[1] = cvt_tf32(PS(prv, r0 + 8, kc * 8 + qc));
                a[2] = cvt_tf32(PS(prv, r0, kc * 8 + qc + 4));
                a[3] = cvt_tf32(PS(prv, r0 + 8, kc * 8 + qc + 4));
#pragma unroll
                for (int nt = 0; nt < 4; nt++) {
                    int dcol = kg * 32 + nt * 8 + (lane >> 2);
                    mma8(oacc[nt], a, VSU(prv, kc * 8 + qc, dcol),
                         VSU(prv, kc * 8 + qc + 4, dcol));
                }
            }
#pragma unroll
            for (int j = 0; j < 4; j++) {
                int i = tid + j * 512;
                int r = i >> 4, cc = (i & 15) * 4;
                *(float4*)(arow + (size_t)r * TK_ + (kb - 64) + cc) =
                    *(float4*)&PS(prv, r, cc);
            }
        }

        cp_wait<0>();     // V(kt), K(kt+1), mask(kt+1) landed
        // convert freshly-landed tiles to tf32 in place (own chunks only)
        if (kt + 1 < NT_) {
#pragma unroll
            for (int j = 0; j < 2; j++) cvt_chunk(&KS(prv, rr + j * 32, c4));
        }
#pragma unroll
        for (int j = 0; j < 2; j++) cvt_chunk(&VS(cur, rr + j * 32, c4));
        __syncthreads();  // publishes Ps[cur] + converted tiles
    }

    // ---- flush: PV + attn store for the last tile ----
    {
        const int lst = (NT_ - 1) & 1;
        const int kb = (NT_ - 1) * 64;
#pragma unroll
        for (int j = 0; j < 4; j++) {
            int i = tid + j * 512;
            int r = i >> 4, cc = (i & 15) * 4;
            *(float4*)(arow + (size_t)r * TK_ + kb + cc) = *(float4*)&PS(lst, r, cc);
        }
#pragma unroll
        for (int kc = 0; kc < 8; kc++) {
            unsigned a[4];
            a[0] = cvt_tf32(PS(lst, r0, kc * 8 + qc));
            a[1] = cvt_tf32(PS(lst, r0 + 8, kc * 8 + qc));
            a[2] = cvt_tf32(PS(lst, r0, kc * 8 + qc + 4));
            a[3] = cvt_tf32(PS(lst, r0 + 8, kc * 8 + qc + 4));
#pragma unroll
            for (int nt = 0; nt < 4; nt++) {
                int dcol = kg * 32 + nt * 8 + (lane >> 2);
                mma8(oacc[nt], a, VSU(lst, kc * 8 + qc, dcol),
                     VSU(lst, kc * 8 + qc + 4, dcol));
            }
        }
    }

    // ---- rowsum reduction: quad lanes, then the two kg warps per rowgroup ----
    rs0 += __shfl_xor_sync(0xFFFFFFFFu, rs0, 1);
    rs0 += __shfl_xor_sync(0xFFFFFFFFu, rs0, 2);
    rs1 += __shfl_xor_sync(0xFFFFFFFFu, rs1, 1);
    rs1 += __shfl_xor_sync(0xFFFFFFFFu, rs1, 2);
    if (qc == 0) {
        atomicAdd(&RowRed[r0], rs0);
        atomicAdd(&RowRed[r0 + 8], rs1);
    }
    __syncthreads();
    if (tid < MROWS) {
        float inv = 1.0f / RowRed[tid];
        RowRed[tid] = inv;
        g_rowinv[bb * TQ_ + qbase + tid] = inv;   // publish for rescale kernel
    }
    __syncthreads();

    // ---- write O scaled by 1/rowsum ----
    {
        float inv0 = RowRed[r0];
        float inv1 = RowRed[r0 + 8];
#pragma unroll
        for (int nt = 0; nt < 4; nt++) {
            int dcol = kg * 32 + nt * 8 + 2 * qc;
            size_t oi = ((size_t)(bb * TQ_ + qbase + r0)) * D_ + dcol;
            *(float2*)(out + oi) =
                make_float2(oacc[nt][0] * inv0, oacc[nt][1] * inv0);
            *(float2*)(out + oi + (size_t)8 * D_) =
                make_float2(oacc[nt][2] * inv1, oacc[nt][3] * inv1);
        }
    }
}

// ---------------------------------------------------------------------------
// Streaming normalize: attn[i] *= g_rowinv[row(i)]. Tiny register footprint,
// full occupancy, coalesced float4 grid-stride -> near-peak DRAM.
// ---------------------------------------------------------------------------
__global__ __launch_bounds__(256)
void rescale_attn(float* __restrict__ attn) {
    const size_t N4 = (size_t)B_ * TQ_ * TK_ / 4;   // 67,108,864 float4
    size_t i = (size_t)blockIdx.x * blockDim.x + threadIdx.x;
    const size_t stride = (size_t)gridDim.x * blockDim.x;
    float4* a4 = (float4*)attn;
#pragma unroll 4
    for (; i < N4; i += stride) {
        float inv = g_rowinv[i >> 9];               // 512 float4 per attn row
        float4 x = a4[i];
        x.x *= inv; x.y *= inv; x.z *= inv; x.w *= inv;
        a4[i] = x;
    }
}

static const int kSmemBytes =
    (2 * 64 * STRW + 2 * 64 * STRW + 2 * MROWS * STRW) * 4 + 2 * MROWS * 80 + MROWS * 4;

extern "C" void kernel_launch(void* const* d_in, const int* in_sizes, int n_in,
                              void* d_out, int out_size) {
    const float* q = (const float*)d_in[0];
    const float* k = (const float*)d_in[1];
    const float* v = (const float*)d_in[2];
    const unsigned char* mask = (const unsigned char*)d_in[3];

    float* out = (float*)d_out;                 // [B, TQ, D]
    float* attn = out + (size_t)B_ * TQ_ * D_;  // [B, TQ, TK]

    cudaFuncSetAttribute(attn_fused, cudaFuncAttributeMaxDynamicSharedMemorySize,
                         kSmemBytes);

    detect_mask_kind<<<1, 256>>>(mask);

    dim3 grid(TQ_ / MROWS, B_);
    attn_fused<<<grid, 512, kSmemBytes>>>(q, k, v, mask, out, attn);

    // 16384 blocks x 256 thr, 16 float4 each: full coverage, grid-stride safe.
    rescale_attn<<<16384, 256>>>(attn);
}

// round 16
// speedup vs baseline: 1.1833x; 1.0482x over previous
#include <cuda_runtime.h>
#include <cuda_bf16.h>
#include <cstdint>

#define B_   64
#define TQ_  2048
#define TK_  2048
#define D_   64
#define STRW 68     // words per smem row (64 + 4 pad: conflict-free quad access)
#define MROWS 128   // q-rows per CTA
#define NT_  (TK_ / 64)

// Per-row 1/rowsum, main kernel -> rescale kernel. Static device scratch.
__device__ float g_rowinv[B_ * TQ_];
// Mask element kind: 1 = 1-byte elements (bool/uint8), 0 = 4-byte (int32/float32)
__device__ int g_mask_kind;

__global__ void detect_mask_kind(const unsigned char* __restrict__ m) {
    __shared__ int flag;
    int tid = threadIdx.x;
    if (tid == 0) flag = 0;
    __syncthreads();
    const uint4* m4 = (const uint4*)m;
    uint4 u = m4[tid];  // 256 threads * 16B = 4096 bytes
    unsigned w[4] = {u.x, u.y, u.z, u.w};
    int bad = 0;
#pragma unroll
    for (int i = 0; i < 4; i++) {
        unsigned x = w[i];
        if (!(x == 0u || x == 1u || x == 0x3F800000u)) bad = 1;
    }
    if (bad) atomicOr(&flag, 1);
    __syncthreads();
    if (tid == 0) g_mask_kind = flag ? 1 : 0;
}

// exp(s/8) via MUFU.EX2: 1 FMUL + 1 MUFU, rel err ~2ulp. (The 9-op FFMA
// polynomial this replaces was the longest serial chain in the tile body.)
__device__ __forceinline__ float fexp8(float s) {
    float r;
    float x = s * 0.18033688011112042f;   // log2(e)/8
    asm("ex2.approx.f32 %0, %1;" : "=f"(r) : "f"(x));
    return r;
}

__device__ __forceinline__ unsigned cvt_tf32(float x) {
    unsigned r;
    asm("cvt.rna.tf32.f32 %0, %1;" : "=r"(r) : "f"(x));
    return r;
}

__device__ __forceinline__ void mma8(float c[4], const unsigned a[4],
                                     unsigned b0, unsigned b1) {
    asm("mma.sync.aligned.m16n8k8.row.col.f32.tf32.tf32.f32 "
        "{%0,%1,%2,%3}, {%4,%5,%6,%7}, {%8,%9}, {%0,%1,%2,%3};"
        : "+f"(c[0]), "+f"(c[1]), "+f"(c[2]), "+f"(c[3])
        : "r"(a[0]), "r"(a[1]), "r"(a[2]), "r"(a[3]), "r"(b0), "r"(b1));
}

__device__ __forceinline__ void cp16(void* sdst, const void* gsrc) {
    unsigned s = (unsigned)__cvta_generic_to_shared(sdst);
    asm volatile("cp.async.cg.shared.global [%0], [%1], 16;\n" :: "r"(s), "l"(gsrc));
}
__device__ __forceinline__ void cp_commit() {
    asm volatile("cp.async.commit_group;\n");
}
template <int N>
__device__ __forceinline__ void cp_wait() {
    asm volatile("cp.async.wait_group %0;\n" :: "n"(N));
}

// convert a 16B smem chunk of 4 f32 to tf32 bits, in place
__device__ __forceinline__ void cvt_chunk(float* p) {
    float4 x = *(float4*)p;
    uint4 u = make_uint4(cvt_tf32(x.x), cvt_tf32(x.y), cvt_tf32(x.z), cvt_tf32(x.w));
    *(uint4*)p = u;
}

// ---------------------------------------------------------------------------
// Fused mainloop (R8 skeleton + split rescale + staged tf32 K/V + MUFU exp).
// CTA: 128 q-rows x full TK, 512 threads / 16 warps.
// Ps now holds rna-tf32 bits of the e-values (cvt once at exp output): the
// PV A operands and the attn store both read it directly.
// Writes UNNORMALIZED attn; per-row inverses -> g_rowinv; normalization in
// rescale_attn (separate streaming kernel).
// ---------------------------------------------------------------------------
__global__ __launch_bounds__(512, 1)
void attn_fused(const float* __restrict__ q, const float* __restrict__ k,
                const float* __restrict__ v, const unsigned char* __restrict__ mask,
                float* __restrict__ out, float* __restrict__ attn) {
    extern __shared__ __align__(16) unsigned char smemraw[];
    float* Kb = (float*)smemraw;                         // [2][64][STRW] tf32 K
    float* Vb = Kb + 2 * 64 * STRW;                      // [2][64][STRW] tf32 V
    float* Psb = Vb + 2 * 64 * STRW;                     // [2][128][STRW] tf32 e
    unsigned char* Msb = (unsigned char*)(Psb + 2 * MROWS * STRW);  // [2][128*80]
    float* RowRed = (float*)(Msb + 2 * MROWS * 80);      // [128]

#define KS(st, r, c) Kb[(st) * (64 * STRW) + (r) * STRW + (c)]
#define VS(st, r, c) Vb[(st) * (64 * STRW) + (r) * STRW + (c)]
#define KSU(st, r, c) (*(unsigned*)&KS(st, r, c))
#define VSU(st, r, c) (*(unsigned*)&VS(st, r, c))
#define PS(st, r, c) Psb[(st) * (MROWS * STRW) + (r) * STRW + (c)]
#define PSU(st, r, c) (*(unsigned*)&PS(st, r, c))
#define MS(st, i)    Msb[(st) * (MROWS * 80) + (i)]

    const int tid = threadIdx.x;
    const int wid = tid >> 5;
    const int lane = tid & 31;
    const int bb = blockIdx.y;
    const int qbase = blockIdx.x * MROWS;

    const float* qp = q + ((size_t)bb * TQ_ + qbase) * D_;
    const float* kp = k + (size_t)bb * TK_ * D_;
    const float* vp = v + (size_t)bb * TK_ * D_;
    float* arow = attn + ((size_t)bb * TQ_ + qbase) * TK_;
    const size_t mbase = ((size_t)bb * TQ_ + qbase) * TK_;
    const int mask_is_byte = g_mask_kind;

    if (tid < MROWS) RowRed[tid] = 0.0f;

    // K/V staging coords: 64x64 f32 tile, 512 threads -> 2 chunks of 16B each
    const int rr = tid >> 4;          // 0..31 ; rows rr, rr+32
    const int c4 = (tid & 15) * 4;
    // byte-mask staging: 128 rows x 64B -> 1 chunk of 16B per thread
    const int mr = tid >> 2;          // 0..127
    const int mseg = (tid & 3) * 16;

    // ---- prologue: prefetch K(0), mask(0) ----
#pragma unroll
    for (int j = 0; j < 2; j++)
        cp16(&KS(0, rr + j * 32, c4), kp + (size_t)(rr + j * 32) * D_ + c4);
    if (mask_is_byte) {
        cp16(&MS(0, mr * 80 + mseg), mask + mbase + (size_t)mr * TK_ + mseg);
    } else {
        const int* mi = (const int*)mask;
#pragma unroll
        for (int j = 0; j < 4; j++) {
            int i4 = tid + j * 512;
            int r = i4 >> 4, cc = (i4 & 15) * 4;
            int4 mm = *(const int4*)(mi + mbase + (size_t)r * TK_ + cc);
            uchar4 pk;
            pk.x = mm.x ? 1 : 0; pk.y = mm.y ? 1 : 0;
            pk.z = mm.z ? 1 : 0; pk.w = mm.w ? 1 : 0;
            *(uchar4*)&MS(0, r * 80 + cc) = pk;
        }
    }
    cp_commit();

    // Stage Q (128x64) into Ps[0] (raw f32), then to tf32 A fragments
#pragma unroll
    for (int j = 0; j < 4; j++) {
        int r = rr + j * 32;
        *(float4*)&PS(0, r, c4) = *(const float4*)(qp + r * D_ + c4);
    }
    __syncthreads();

    const int rg = wid >> 1;                 // 0..7
    const int kg = wid & 1;
    const int r0 = rg * 16 + (lane >> 2);    // 0..127
    const int qc = lane & 3;

    unsigned qa[8][4];
#pragma unroll
    for (int kc = 0; kc < 8; kc++) {
        qa[kc][0] = cvt_tf32(PS(0, r0, kc * 8 + qc));
        qa[kc][1] = cvt_tf32(PS(0, r0 + 8, kc * 8 + qc));
        qa[kc][2] = cvt_tf32(PS(0, r0, kc * 8 + qc + 4));
        qa[kc][3] = cvt_tf32(PS(0, r0 + 8, kc * 8 + qc + 4));
    }
    cp_wait<0>();     // K0/M0 arrived
    // convert K(0) to tf32 in place (each thread converts what it staged)
#pragma unroll
    for (int j = 0; j < 2; j++) cvt_chunk(&KS(0, rr + j * 32, c4));
    __syncthreads();  // qa built; Ps[0] free; converted K tile visible to all

    float oacc[4][4];
#pragma unroll
    for (int nt = 0; nt < 4; nt++)
#pragma unroll
        for (int i = 0; i < 4; i++) oacc[nt][i] = 0.0f;
    float rs0 = 0.0f, rs1 = 0.0f;

    for (int kt = 0; kt < NT_; kt++) {
        const int kb = kt * 64;
        const int cur = kt & 1;
        const int prv = cur ^ 1;

        // --- prefetch: V(kt) -> Vb[cur]; K(kt+1)+mask(kt+1) -> [cur^1] ---
#pragma unroll
        for (int j = 0; j < 2; j++) {
            int r = rr + j * 32;
            cp16(&VS(cur, r, c4), vp + (size_t)(kb + r) * D_ + c4);
        }
        if (kt + 1 < NT_) {
            const int kb2 = kb + 64;
#pragma unroll
            for (int j = 0; j < 2; j++) {
                int r = rr + j * 32;
                cp16(&KS(prv, r, c4), kp + (size_t)(kb2 + r) * D_ + c4);
            }
            if (mask_is_byte) {
                cp16(&MS(prv, mr * 80 + mseg),
                     mask + mbase + (size_t)mr * TK_ + kb2 + mseg);
            } else {
                const int* mi = (const int*)mask;
#pragma unroll
                for (int j = 0; j < 4; j++) {
                    int i4 = tid + j * 512;
                    int r = i4 >> 4, cc = (i4 & 15) * 4;
                    int4 mm = *(const int4*)(mi + mbase + (size_t)r * TK_ + kb2 + cc);
                    uchar4 pk;
                    pk.x = mm.x ? 1 : 0; pk.y = mm.y ? 1 : 0;
                    pk.z = mm.z ? 1 : 0; pk.w = mm.w ? 1 : 0;
                    *(uchar4*)&MS(prv, r * 80 + cc) = pk;
                }
            }
        }
        cp_commit();

        // --- S = Q * K^T for this warp's 16x32 subtile (tile kt) ---
        // K already tf32: plain LDS -> HMMA
        float c[4][4];
#pragma unroll
        for (int nt = 0; nt < 4; nt++)
#pragma unroll
            for (int i = 0; i < 4; i++) c[nt][i] = 0.0f;

#pragma unroll
        for (int kc = 0; kc < 8; kc++) {
#pragma unroll
            for (int nt = 0; nt < 4; nt++) {
                int key = kg * 32 + nt * 8 + (lane >> 2);
                mma8(c[nt], qa[kc], KSU(cur, key, kc * 8 + qc),
                     KSU(cur, key, kc * 8 + qc + 4));
            }
        }

        // --- mask + exp (MUFU) -> Ps[cur] as tf32 bits, rowsum in regs ---
#pragma unroll
        for (int nt = 0; nt < 4; nt++) {
            int col = kg * 32 + nt * 8 + 2 * qc;
            float e00 = MS(cur, r0 * 80 + col)           ? 0.0f : fexp8(c[nt][0]);
            float e01 = MS(cur, r0 * 80 + col + 1)       ? 0.0f : fexp8(c[nt][1]);
            float e10 = MS(cur, (r0 + 8) * 80 + col)     ? 0.0f : fexp8(c[nt][2]);
            float e11 = MS(cur, (r0 + 8) * 80 + col + 1) ? 0.0f : fexp8(c[nt][3]);
            rs0 += e00 + e01;
            rs1 += e10 + e11;
            *(uint2*)&PS(cur, r0, col) =
                make_uint2(cvt_tf32(e00), cvt_tf32(e01));
            *(uint2*)&PS(cur, r0 + 8, col) =
                make_uint2(cvt_tf32(e10), cvt_tf32(e11));
        }

        // --- deferred: PV(kt-1) + attn store(kt-1) from Ps[prv]/V[prv] ---
        // P and V already tf32 bits: plain LDS operands
        if (kt > 0) {
#pragma unroll
            for (int kc = 0; kc < 8; kc++) {
                unsigned a[4];
                a[0] = PSU(prv, r0, kc * 8 + qc);
                a[1] = PSU(prv, r0 + 8, kc * 8 + qc);
                a[2] = PSU(prv, r0, kc * 8 + qc + 4);
                a[3] = PSU(prv, r0 + 8, kc * 8 + qc + 4);
#pragma unroll
                for (int nt = 0; nt < 4; nt++) {
                    int dcol = kg * 32 + nt * 8 + (lane >> 2);
                    mma8(oacc[nt], a, VSU(prv, kc * 8 + qc, dcol),
                         VSU(prv, kc * 8 + qc + 4, dcol));
                }
            }
#pragma unroll
            for (int j = 0; j < 4; j++) {
                int i = tid + j * 512;
                int r = i >> 4, cc = (i & 15) * 4;
                *(float4*)(arow + (size_t)r * TK_ + (kb - 64) + cc) =
                    *(float4*)&PS(prv, r, cc);
            }
        }

        cp_wait<0>();     // V(kt), K(kt+1), mask(kt+1) landed
        // convert freshly-landed tiles to tf32 in place (own chunks only)
        if (kt + 1 < NT_) {
#pragma unroll
            for (int j = 0; j < 2; j++) cvt_chunk(&KS(prv, rr + j * 32, c4));
        }
#pragma unroll
        for (int j = 0; j < 2; j++) cvt_chunk(&VS(cur, rr + j * 32, c4));
        __syncthreads();  // publishes Ps[cur] + converted tiles
    }

    // ---- flush: PV + attn store for the last tile ----
    {
        const int lst = (NT_ - 1) & 1;
        const int kb = (NT_ - 1) * 64;
#pragma unroll
        for (int j = 0; j < 4; j++) {
            int i = tid + j * 512;
            int r = i >> 4, cc = (i & 15) * 4;
            *(float4*)(arow + (size_t)r * TK_ + kb + cc) = *(float4*)&PS(lst, r, cc);
        }
#pragma unroll
        for (int kc = 0; kc < 8; kc++) {
            unsigned a[4];
            a[0] = PSU(lst, r0, kc * 8 + qc);
            a[1] = PSU(lst, r0 + 8, kc * 8 + qc);
            a[2] = PSU(lst, r0, kc * 8 + qc + 4);
            a[3] = PSU(lst, r0 + 8, kc * 8 + qc + 4);
#pragma unroll
            for (int nt = 0; nt < 4; nt++) {
                int dcol = kg * 32 + nt * 8 + (lane >> 2);
                mma8(oacc[nt], a, VSU(lst, kc * 8 + qc, dcol),
                     VSU(lst, kc * 8 + qc + 4, dcol));
            }
        }
    }

    // ---- rowsum reduction: quad lanes, then the two kg warps per rowgroup ----
    rs0 += __shfl_xor_sync(0xFFFFFFFFu, rs0, 1);
    rs0 += __shfl_xor_sync(0xFFFFFFFFu, rs0, 2);
    rs1 += __shfl_xor_sync(0xFFFFFFFFu, rs1, 1);
    rs1 += __shfl_xor_sync(0xFFFFFFFFu, rs1, 2);
    if (qc == 0) {
        atomicAdd(&RowRed[r0], rs0);
        atomicAdd(&RowRed[r0 + 8], rs1);
    }
    __syncthreads();
    if (tid < MROWS) {
        float inv = 1.0f / RowRed[tid];
        RowRed[tid] = inv;
        g_rowinv[bb * TQ_ + qbase + tid] = inv;   // publish for rescale kernel
    }
    __syncthreads();

    // ---- write O scaled by 1/rowsum ----
    {
        float inv0 = RowRed[r0];
        float inv1 = RowRed[r0 + 8];
#pragma unroll
        for (int nt = 0; nt < 4; nt++) {
            int dcol = kg * 32 + nt * 8 + 2 * qc;
            size_t oi = ((size_t)(bb * TQ_ + qbase + r0)) * D_ + dcol;
            *(float2*)(out + oi) =
                make_float2(oacc[nt][0] * inv0, oacc[nt][1] * inv0);
            *(float2*)(out + oi + (size_t)8 * D_) =
                make_float2(oacc[nt][2] * inv1, oacc[nt][3] * inv1);
        }
    }
}

// ---------------------------------------------------------------------------
// Streaming normalize: attn[i] *= g_rowinv[row(i)]. Tiny register footprint,
// full occupancy, coalesced float4 grid-stride -> near-peak DRAM.
// ---------------------------------------------------------------------------
__global__ __launch_bounds__(256)
void rescale_attn(float* __restrict__ attn) {
    const size_t N4 = (size_t)B_ * TQ_ * TK_ / 4;   // 67,108,864 float4
    size_t i = (size_t)blockIdx.x * blockDim.x + threadIdx.x;
    const size_t stride = (size_t)gridDim.x * blockDim.x;
    float4* a4 = (float4*)attn;
#pragma unroll 4
    for (; i < N4; i += stride) {
        float inv = g_rowinv[i >> 9];               // 512 float4 per attn row
        float4 x = a4[i];
        x.x *= inv; x.y *= inv; x.z *= inv; x.w *= inv;
        a4[i] = x;
    }
}

static const int kSmemBytes =
    (2 * 64 * STRW + 2 * 64 * STRW + 2 * MROWS * STRW) * 4 + 2 * MROWS * 80 + MROWS * 4;

extern "C" void kernel_launch(void* const* d_in, const int* in_sizes, int n_in,
                              void* d_out, int out_size) {
    const float* q = (const float*)d_in[0];
    const float* k = (const float*)d_in[1];
    const float* v = (const float*)d_in[2];
    const unsigned char* mask = (const unsigned char*)d_in[3];

    float* out = (float*)d_out;                 // [B, TQ, D]
    float* attn = out + (size_t)B_ * TQ_ * D_;  // [B, TQ, TK]

    cudaFuncSetAttribute(attn_fused, cudaFuncAttributeMaxDynamicSharedMemorySize,
                         kSmemBytes);

    detect_mask_kind<<<1, 256>>>(mask);

    dim3 grid(TQ_ / MROWS, B_);
    attn_fused<<<grid, 512, kSmemBytes>>>(q, k, v, mask, out, attn);

    // 16384 blocks x 256 thr, 16 float4 each: full coverage, grid-stride safe.
    rescale_attn<<<16384, 256>>>(attn);
}